// round 5
// baseline (speedup 1.0000x reference)
#include <cuda_runtime.h>
#include <math.h>

// Problem constants: B=64, S=2048, I=256, H=256, G=2H=512
#define BATCH 64
#define SEQ   2048
#define HID   256
#define GATES 512

// -------- scratch (static device arrays; no allocation) --------
__device__ float g_gx[67108864];        // (B*S, 512) fp32 = 256 MB
__device__ float g_WhT0[HID * GATES];   // [j][g]
__device__ float g_WiT1[HID * GATES];   // [j][g]
__device__ float g_WhT1[HID * GATES];   // [j][g]

// ---------------------------------------------------------------
// Kernel 0: transpose recurrent/input-1 weights to [j][g] layout.
// ---------------------------------------------------------------
__global__ void prep_kernel(const float* __restrict__ Wh0,
                            const float* __restrict__ Wi1,
                            const float* __restrict__ Wh1)
{
    int idx = blockIdx.x * 256 + threadIdx.x;
    const int per = GATES * HID;      // 131072
    if (idx < 3 * per) {
        int m = idx / per;
        int e = idx - m * per;
        int g = e >> 8;               // /256
        int j = e & 255;
        const float* src = (m == 0) ? Wh0 : (m == 1) ? Wi1 : Wh1;
        float*       dst = (m == 0) ? g_WhT0 : (m == 1) ? g_WiT1 : g_WhT1;
        dst[j * GATES + g] = src[g * HID + j];
    }
}

// ---------------------------------------------------------------
// Kernel 1: gx0 = (x @ Wi0^T + bi0) + bh0
// Per-output: single accumulator, strictly ascending k, FMA — this is the
// reduction order of both Eigen gebp (CPU ref) and cublas SIMT sgemm (GPU ref).
// Bias adds kept separate and in reference order.
// ---------------------------------------------------------------
__global__ void __launch_bounds__(256, 2)
gemm_gx_kernel(const float* __restrict__ x,
               const float* __restrict__ Wi0,
               const float* __restrict__ bi0,
               const float* __restrict__ bh0)
{
    __shared__ float As[32][68];   // [k][m]
    __shared__ float Bs[32][68];   // [k][n]

    const int m0  = blockIdx.x * 64;
    const int n0  = blockIdx.y * 64;
    const int tid = threadIdx.x;
    const int tx  = tid & 15;
    const int ty  = tid >> 4;

    float acc[4][4];
#pragma unroll
    for (int i = 0; i < 4; i++)
#pragma unroll
        for (int j = 0; j < 4; j++) acc[i][j] = 0.f;

    for (int k0 = 0; k0 < 256; k0 += 32) {
#pragma unroll
        for (int v = 0; v < 2; v++) {
            int idx = tid + v * 256;
            int r   = idx >> 3;
            int kk  = (idx & 7) << 2;
            float4 av = *reinterpret_cast<const float4*>(
                x + (size_t)(m0 + r) * 256 + (k0 + kk));
            As[kk + 0][r] = av.x; As[kk + 1][r] = av.y;
            As[kk + 2][r] = av.z; As[kk + 3][r] = av.w;
            float4 bv = *reinterpret_cast<const float4*>(
                Wi0 + (size_t)(n0 + r) * 256 + (k0 + kk));
            Bs[kk + 0][r] = bv.x; Bs[kk + 1][r] = bv.y;
            Bs[kk + 2][r] = bv.z; Bs[kk + 3][r] = bv.w;
        }
        __syncthreads();
#pragma unroll
        for (int k = 0; k < 32; k++) {
            float4 av = *reinterpret_cast<const float4*>(&As[k][ty << 2]);
            float4 bv = *reinterpret_cast<const float4*>(&Bs[k][tx << 2]);
            float aa[4] = {av.x, av.y, av.z, av.w};
            float bb[4] = {bv.x, bv.y, bv.z, bv.w};
#pragma unroll
            for (int i = 0; i < 4; i++)
#pragma unroll
                for (int j = 0; j < 4; j++)
                    acc[i][j] = __fmaf_rn(aa[i], bb[j], acc[i][j]);
        }
        __syncthreads();
    }

    float4 b1 = *reinterpret_cast<const float4*>(bi0 + n0 + (tx << 2));
    float4 b2 = *reinterpret_cast<const float4*>(bh0 + n0 + (tx << 2));

#pragma unroll
    for (int i = 0; i < 4; i++) {
        int r = m0 + (ty << 2) + i;
        float4 o;
        o.x = __fadd_rn(__fadd_rn(acc[i][0], b1.x), b2.x);
        o.y = __fadd_rn(__fadd_rn(acc[i][1], b1.y), b2.y);
        o.z = __fadd_rn(__fadd_rn(acc[i][2], b1.z), b2.z);
        o.w = __fadd_rn(__fadd_rn(acc[i][3], b1.w), b2.w);
        *reinterpret_cast<float4*>(g_gx + (size_t)r * GATES + n0 + (tx << 2)) = o;
    }
}

// ---------------------------------------------------------------
// Strictly-ascending active-row sum for 4 consecutive gates.
// Each component chain is a single accumulator in ascending j order,
// bit-identical to the dense ascending-k FMA dot with binary h.
// 16-deep register prefetch for memory-level parallelism.
// ---------------------------------------------------------------
__device__ __forceinline__ float4 matvec4(const float* __restrict__ Wbase,
                                          const int* __restrict__ lst, int n)
{
    float4 m = make_float4(0.f, 0.f, 0.f, 0.f);
    int i = 0;
    while (i < n) {
        float4 w[16];
        int lim = n - i; if (lim > 16) lim = 16;
#pragma unroll
        for (int u = 0; u < 16; u++) {
            if (u < lim) {
                int j = lst[i + u];
                w[u] = *reinterpret_cast<const float4*>(Wbase + ((size_t)j << 9));
            }
        }
#pragma unroll
        for (int u = 0; u < 16; u++) {
            if (u < lim) {
                m.x = __fadd_rn(m.x, w[u].x);
                m.y = __fadd_rn(m.y, w[u].y);
                m.z = __fadd_rn(m.z, w[u].z);
                m.w = __fadd_rn(m.w, w[u].w);
            }
        }
        i += 16;
    }
    return m;
}

// XLA logistic expansion: 1 / (1 + exp(-x)), all f32 rn ops.
// exp computed in fp64 then rounded -> (near) correctly-rounded f32 exp.
__device__ __forceinline__ float sigmoid_ref(float g)
{
    float ef = (float)exp(-(double)g);
    return __fdiv_rn(1.0f, __fadd_rn(1.0f, ef));
}

// ---------------------------------------------------------------
// Kernel 2: fused 2-layer spiking-LSTM scan. One CTA per batch.
// 512 threads:
//   warps 0-3  (tid   0-127): gate quads (float4) for matvec sums
//   warps 4-7  (tid 128-255): layer-1 Wh1 matvec (parallel with Wi1)
//   tid < 256: cell update + spike + list build
// ---------------------------------------------------------------
__global__ void __launch_bounds__(512, 1)
recurrent_kernel(const float* __restrict__ bi1,
                 const float* __restrict__ bh1,
                 float* __restrict__ out)
{
    const int b    = blockIdx.x;
    const int tid  = threadIdx.x;
    const int lane = tid & 31;
    const int warp = tid >> 5;

    __shared__ float c0s[HID], c1s[HID];
    __shared__ float gxs[GATES];
    __shared__ float gsm[GATES];
    __shared__ float mh_sm[GATES];
    __shared__ int   lst0[HID], lst1[HID];
    __shared__ int   wb[8];
    __shared__ int   n0s, n1s;

    if (tid < HID) { c0s[tid] = 0.f; c1s[tid] = 0.f; }
    if (tid == 0)  { n0s = 0; n1s = 0; }

    // layer-1 biases, kept separate (reference grouping)
    float4 bi1v = make_float4(0,0,0,0), bh1v = make_float4(0,0,0,0);
    if (tid < 128) {
        bi1v = *reinterpret_cast<const float4*>(bi1 + (tid << 2));
        bh1v = *reinterpret_cast<const float4*>(bh1 + (tid << 2));
    }
    __syncthreads();

    const float* gxb  = g_gx + (size_t)b * ((size_t)SEQ * GATES);
    float*       outb = out  + (size_t)b * ((size_t)SEQ * HID);

    for (int t = 0; t < SEQ; ++t) {
        // stage this step's precomputed input gates
        gxs[tid] = gxb[(size_t)t * GATES + tid];

        // ---------------- layer 0 ----------------
        int n0 = n0s;                 // h0(t-1) active count (stable since last bar)
        float4 m0v = make_float4(0,0,0,0);
        if (tid < 128)
            m0v = matvec4(g_WhT0 + (tid << 2), lst0, n0);
        __syncthreads();              // gxs staged, matvec done
        if (tid < 128) {
            float4 gx4 = *reinterpret_cast<const float4*>(&gxs[tid << 2]);
            float4 g4;
            g4.x = __fadd_rn(gx4.x, m0v.x);   // g_t + h @ Wh0^T
            g4.y = __fadd_rn(gx4.y, m0v.y);
            g4.z = __fadd_rn(gx4.z, m0v.z);
            g4.w = __fadd_rn(gx4.w, m0v.w);
            *reinterpret_cast<float4*>(&gsm[tid << 2]) = g4;
        }
        __syncthreads();

        bool p = false; unsigned bal = 0;
        if (tid < HID) {
            float g  = gsm[tid];
            float f  = sigmoid_ref(g);
            float ct = gsm[tid + HID];
            float c  = __fadd_rn(__fmul_rn(f, c0s[tid]),
                                 __fmul_rn(__fsub_rn(1.0f, f), ct));
            c0s[tid] = c;
            p = (c > 0.f);
            bal = __ballot_sync(0xffffffffu, p);
            if (lane == 0) wb[warp] = __popc(bal);
        }
        __syncthreads();
        if (tid == 0) {
            int acc = 0;
#pragma unroll
            for (int i = 0; i < 8; i++) { int c = wb[i]; wb[i] = acc; acc += c; }
            n0s = acc;
        }
        __syncthreads();
        if (p) lst0[wb[warp] + __popc(bal & ((1u << lane) - 1u))] = tid;
        __syncthreads();

        // ---------------- layer 1 ----------------
        // gates = ((Wi1 . h0_new + bi1) + bh1) + Wh1 . h1_old
        int n0n = n0s;
        int n1  = n1s;
        if (tid < 128) {
            float4 mi = matvec4(g_WiT1 + (tid << 2), lst0, n0n);
            // stash partial: gi = (mi + bi1) + bh1
            float4 gi;
            gi.x = __fadd_rn(__fadd_rn(mi.x, bi1v.x), bh1v.x);
            gi.y = __fadd_rn(__fadd_rn(mi.y, bi1v.y), bh1v.y);
            gi.z = __fadd_rn(__fadd_rn(mi.z, bi1v.z), bh1v.z);
            gi.w = __fadd_rn(__fadd_rn(mi.w, bi1v.w), bh1v.w);
            *reinterpret_cast<float4*>(&gxs[tid << 2]) = gi;   // reuse gxs
        } else if (tid < 256) {
            int q = (tid - 128) << 2;
            float4 mh = matvec4(g_WhT1 + q, lst1, n1);
            *reinterpret_cast<float4*>(&mh_sm[q]) = mh;
        }
        __syncthreads();
        if (tid < 128) {
            float4 gi = *reinterpret_cast<const float4*>(&gxs[tid << 2]);
            float4 mh = *reinterpret_cast<const float4*>(&mh_sm[tid << 2]);
            float4 g4;
            g4.x = __fadd_rn(gi.x, mh.x);
            g4.y = __fadd_rn(gi.y, mh.y);
            g4.z = __fadd_rn(gi.z, mh.z);
            g4.w = __fadd_rn(gi.w, mh.w);
            *reinterpret_cast<float4*>(&gsm[tid << 2]) = g4;
        }
        __syncthreads();

        p = false; bal = 0;
        if (tid < HID) {
            float g  = gsm[tid];
            float f  = sigmoid_ref(g);
            float ct = gsm[tid + HID];
            float c  = __fadd_rn(__fmul_rn(f, c1s[tid]),
                                 __fmul_rn(__fsub_rn(1.0f, f), ct));
            c1s[tid] = c;
            float h  = (c > 0.f) ? 1.f : 0.f;
            p = (c > 0.f);
            outb[(size_t)t * HID + tid] = h;
            bal = __ballot_sync(0xffffffffu, p);
            if (lane == 0) wb[warp] = __popc(bal);
        }
        __syncthreads();
        if (tid == 0) {
            int acc = 0;
#pragma unroll
            for (int i = 0; i < 8; i++) { int c = wb[i]; wb[i] = acc; acc += c; }
            n1s = acc;
        }
        __syncthreads();
        if (p) lst1[wb[warp] + __popc(bal & ((1u << lane) - 1u))] = tid;
        __syncthreads();
    }

    // finals: h_n (2,B,H) then c_n (2,B,H) after the (B,S,H) output
    if (tid < HID) {
        const size_t HN = (size_t)BATCH * SEQ * HID;
        const size_t CN = HN + (size_t)2 * BATCH * HID;
        out[HN + ((size_t)0 * BATCH + b) * HID + tid] = (c0s[tid] > 0.f) ? 1.f : 0.f;
        out[HN + ((size_t)1 * BATCH + b) * HID + tid] = (c1s[tid] > 0.f) ? 1.f : 0.f;
        out[CN + ((size_t)0 * BATCH + b) * HID + tid] = c0s[tid];
        out[CN + ((size_t)1 * BATCH + b) * HID + tid] = c1s[tid];
    }
}

// ---------------------------------------------------------------
extern "C" void kernel_launch(void* const* d_in, const int* in_sizes, int n_in,
                              void* d_out, int out_size)
{
    const float* x   = (const float*)d_in[0];
    const float* Wi0 = (const float*)d_in[1];
    const float* bi0 = (const float*)d_in[2];
    const float* Wh0 = (const float*)d_in[3];
    const float* bh0 = (const float*)d_in[4];
    const float* Wi1 = (const float*)d_in[5];
    const float* bi1 = (const float*)d_in[6];
    const float* Wh1 = (const float*)d_in[7];
    const float* bh1 = (const float*)d_in[8];
    float* out = (float*)d_out;

    prep_kernel<<<1536, 256>>>(Wh0, Wi1, Wh1);

    dim3 gg(2048, 8);
    gemm_gx_kernel<<<gg, 256>>>(x, Wi0, bi0, bh0);

    recurrent_kernel<<<BATCH, 512>>>(bi1, bh1, out);
}

// round 6
// speedup vs baseline: 3.1010x; 3.1010x over previous
#include <cuda_runtime.h>
#include <math.h>

// Problem constants: B=64, S=2048, I=256, H=256, G=2H=512
#define BATCH 64
#define SEQ   2048
#define HID   256
#define GATES 512
#define WROWS 272          // 256 real rows + 16 zero pad rows
#define ZROW  256          // index of a guaranteed all-zero row

// -------- scratch (static device arrays; no allocation) --------
__device__ float g_gx[67108864];          // (B*S, 512) fp32 = 256 MB
__device__ float g_WhT0[WROWS * GATES];   // [j][g], rows >=256 are zero
__device__ float g_WiT1[WROWS * GATES];
__device__ float g_WhT1[WROWS * GATES];

// ---------------------------------------------------------------
// Kernel 0: transpose weights into padded [j][g] layout; zero pad rows.
// ---------------------------------------------------------------
__global__ void prep_kernel(const float* __restrict__ Wh0,
                            const float* __restrict__ Wi1,
                            const float* __restrict__ Wh1)
{
    int idx = blockIdx.x * 256 + threadIdx.x;
    const int perp = WROWS * GATES;       // 139264
    if (idx < 3 * perp) {
        int m = idx / perp;
        int e = idx - m * perp;
        int j = e >> 9;                   // row
        int g = e & 511;                  // col
        const float* src = (m == 0) ? Wh0 : (m == 1) ? Wi1 : Wh1;
        float*       dst = (m == 0) ? g_WhT0 : (m == 1) ? g_WiT1 : g_WhT1;
        dst[e] = (j < HID) ? src[g * HID + j] : 0.0f;
    }
}

// ---------------------------------------------------------------
// Kernel 1: gx0 = (x @ Wi0^T + bi0) + bh0   (unchanged — passed)
// Per-output: single accumulator, strictly ascending k, FMA.
// ---------------------------------------------------------------
__global__ void __launch_bounds__(256, 2)
gemm_gx_kernel(const float* __restrict__ x,
               const float* __restrict__ Wi0,
               const float* __restrict__ bi0,
               const float* __restrict__ bh0)
{
    __shared__ float As[32][68];
    __shared__ float Bs[32][68];

    const int m0  = blockIdx.x * 64;
    const int n0  = blockIdx.y * 64;
    const int tid = threadIdx.x;
    const int tx  = tid & 15;
    const int ty  = tid >> 4;

    float acc[4][4];
#pragma unroll
    for (int i = 0; i < 4; i++)
#pragma unroll
        for (int j = 0; j < 4; j++) acc[i][j] = 0.f;

    for (int k0 = 0; k0 < 256; k0 += 32) {
#pragma unroll
        for (int v = 0; v < 2; v++) {
            int idx = tid + v * 256;
            int r   = idx >> 3;
            int kk  = (idx & 7) << 2;
            float4 av = *reinterpret_cast<const float4*>(
                x + (size_t)(m0 + r) * 256 + (k0 + kk));
            As[kk + 0][r] = av.x; As[kk + 1][r] = av.y;
            As[kk + 2][r] = av.z; As[kk + 3][r] = av.w;
            float4 bv = *reinterpret_cast<const float4*>(
                Wi0 + (size_t)(n0 + r) * 256 + (k0 + kk));
            Bs[kk + 0][r] = bv.x; Bs[kk + 1][r] = bv.y;
            Bs[kk + 2][r] = bv.z; Bs[kk + 3][r] = bv.w;
        }
        __syncthreads();
#pragma unroll
        for (int k = 0; k < 32; k++) {
            float4 av = *reinterpret_cast<const float4*>(&As[k][ty << 2]);
            float4 bv = *reinterpret_cast<const float4*>(&Bs[k][tx << 2]);
            float aa[4] = {av.x, av.y, av.z, av.w};
            float bb[4] = {bv.x, bv.y, bv.z, bv.w};
#pragma unroll
            for (int i = 0; i < 4; i++)
#pragma unroll
                for (int j = 0; j < 4; j++)
                    acc[i][j] = __fmaf_rn(aa[i], bb[j], acc[i][j]);
        }
        __syncthreads();
    }

    float4 b1 = *reinterpret_cast<const float4*>(bi0 + n0 + (tx << 2));
    float4 b2 = *reinterpret_cast<const float4*>(bh0 + n0 + (tx << 2));

#pragma unroll
    for (int i = 0; i < 4; i++) {
        int r = m0 + (ty << 2) + i;
        float4 o;
        o.x = __fadd_rn(__fadd_rn(acc[i][0], b1.x), b2.x);
        o.y = __fadd_rn(__fadd_rn(acc[i][1], b1.y), b2.y);
        o.z = __fadd_rn(__fadd_rn(acc[i][2], b1.z), b2.z);
        o.w = __fadd_rn(__fadd_rn(acc[i][3], b1.w), b2.w);
        *reinterpret_cast<float4*>(g_gx + (size_t)r * GATES + n0 + (tx << 2)) = o;
    }
}

// ---------------------------------------------------------------
// Scalar active-row sum for one gate column.
// n16 is a multiple of 16 (list padded with ZROW -> +0.0f adds, which are
// bit-identical no-ops on a single ascending accumulator chain).
// 16 unconditional independent loads per batch -> MLP=16 per thread.
// ---------------------------------------------------------------
__device__ __forceinline__ float matvec_col(const float* __restrict__ Wg,
                                            const int* __restrict__ lst,
                                            int n16)
{
    float acc = 0.f;
    const int4* l4 = reinterpret_cast<const int4*>(lst);
    int nb = n16 >> 4;
    for (int ibt = 0; ibt < nb; ibt++) {
        int4 a = l4[ibt * 4 + 0];
        int4 b = l4[ibt * 4 + 1];
        int4 c = l4[ibt * 4 + 2];
        int4 d = l4[ibt * 4 + 3];
        float w0  = __ldg(Wg + (a.x << 9));
        float w1  = __ldg(Wg + (a.y << 9));
        float w2  = __ldg(Wg + (a.z << 9));
        float w3  = __ldg(Wg + (a.w << 9));
        float w4  = __ldg(Wg + (b.x << 9));
        float w5  = __ldg(Wg + (b.y << 9));
        float w6  = __ldg(Wg + (b.z << 9));
        float w7  = __ldg(Wg + (b.w << 9));
        float w8  = __ldg(Wg + (c.x << 9));
        float w9  = __ldg(Wg + (c.y << 9));
        float w10 = __ldg(Wg + (c.z << 9));
        float w11 = __ldg(Wg + (c.w << 9));
        float w12 = __ldg(Wg + (d.x << 9));
        float w13 = __ldg(Wg + (d.y << 9));
        float w14 = __ldg(Wg + (d.z << 9));
        float w15 = __ldg(Wg + (d.w << 9));
        acc = __fadd_rn(acc, w0);
        acc = __fadd_rn(acc, w1);
        acc = __fadd_rn(acc, w2);
        acc = __fadd_rn(acc, w3);
        acc = __fadd_rn(acc, w4);
        acc = __fadd_rn(acc, w5);
        acc = __fadd_rn(acc, w6);
        acc = __fadd_rn(acc, w7);
        acc = __fadd_rn(acc, w8);
        acc = __fadd_rn(acc, w9);
        acc = __fadd_rn(acc, w10);
        acc = __fadd_rn(acc, w11);
        acc = __fadd_rn(acc, w12);
        acc = __fadd_rn(acc, w13);
        acc = __fadd_rn(acc, w14);
        acc = __fadd_rn(acc, w15);
    }
    return acc;
}

// XLA logistic: 1/(1+exp(-x)), exp via fp64 rounded to f32 (unchanged — passed).
__device__ __forceinline__ float sigmoid_ref(float g)
{
    float ef = (float)exp(-(double)g);
    return __fdiv_rn(1.0f, __fadd_rn(1.0f, ef));
}

// ---------------------------------------------------------------
// Kernel 2: fused 2-layer spiking-LSTM scan. One CTA per batch element.
// 512 threads, one gate per thread. Active lists padded to x16 with ZROW.
// ---------------------------------------------------------------
__global__ void __launch_bounds__(512, 1)
recurrent_kernel(const float* __restrict__ bi1,
                 const float* __restrict__ bh1,
                 float* __restrict__ out)
{
    const int b    = blockIdx.x;
    const int g    = threadIdx.x;      // gate index 0..511
    const int lane = g & 31;
    const int warp = g >> 5;

    __shared__ float c0s[HID], c1s[HID];
    __shared__ float gsm[GATES];
    __shared__ alignas(16) int lst0[WROWS];
    __shared__ alignas(16) int lst1[WROWS];
    __shared__ int wb[8];
    __shared__ int n0e, n0p, n1e, n1p;   // exact / padded counts

    if (g < HID) { c0s[g] = 0.f; c1s[g] = 0.f; }
    if (g == 0)  { n0e = 0; n0p = 0; n1e = 0; n1p = 0; }

    const float bi1v = bi1[g];
    const float bh1v = bh1[g];
    __syncthreads();

    const float* gxb  = g_gx + (size_t)b * ((size_t)SEQ * GATES);
    float*       outb = out  + (size_t)b * ((size_t)SEQ * HID);

    for (int t = 0; t < SEQ; ++t) {
        // streamed, read-once input gates (bypass L1; keep L1 for weights)
        float gxv = __ldcg(gxb + (size_t)t * GATES + g);

        // ---------------- layer 0: gates = gx + Wh0 . h0_old ----------------
        float m0 = matvec_col(g_WhT0 + g, lst0, n0p);
        gsm[g] = __fadd_rn(gxv, m0);
        __syncthreads();

        bool p = false; unsigned bal = 0;
        if (g < HID) {
            float f  = sigmoid_ref(gsm[g]);
            float ct = gsm[g + HID];
            float c  = __fadd_rn(__fmul_rn(f, c0s[g]),
                                 __fmul_rn(__fsub_rn(1.0f, f), ct));
            c0s[g] = c;
            p = (c > 0.f);
            bal = __ballot_sync(0xffffffffu, p);
            if (lane == 0) wb[warp] = __popc(bal);
        }
        __syncthreads();
        if (g == 0) {
            int acc = 0;
#pragma unroll
            for (int i = 0; i < 8; i++) { int c = wb[i]; wb[i] = acc; acc += c; }
            n0e = acc;
            n0p = (acc + 15) & ~15;
        }
        __syncthreads();
        if (p) lst0[wb[warp] + __popc(bal & ((1u << lane) - 1u))] = g;
        if (g < 16) { int idx = n0e + g; if (idx < n0p) lst0[idx] = ZROW; }
        __syncthreads();

        // -------- layer 1: gates = ((Wi1 . h0_new + bi1) + bh1) + Wh1 . h1_old
        float mi = matvec_col(g_WiT1 + g, lst0, n0p);
        float mh = matvec_col(g_WhT1 + g, lst1, n1p);
        gsm[g] = __fadd_rn(__fadd_rn(__fadd_rn(mi, bi1v), bh1v), mh);
        __syncthreads();

        p = false; bal = 0;
        if (g < HID) {
            float f  = sigmoid_ref(gsm[g]);
            float ct = gsm[g + HID];
            float c  = __fadd_rn(__fmul_rn(f, c1s[g]),
                                 __fmul_rn(__fsub_rn(1.0f, f), ct));
            c1s[g] = c;
            float h  = (c > 0.f) ? 1.f : 0.f;
            p = (c > 0.f);
            outb[(size_t)t * HID + g] = h;
            bal = __ballot_sync(0xffffffffu, p);
            if (lane == 0) wb[warp] = __popc(bal);
        }
        __syncthreads();
        if (g == 0) {
            int acc = 0;
#pragma unroll
            for (int i = 0; i < 8; i++) { int c = wb[i]; wb[i] = acc; acc += c; }
            n1e = acc;
            n1p = (acc + 15) & ~15;
        }
        __syncthreads();
        if (p) lst1[wb[warp] + __popc(bal & ((1u << lane) - 1u))] = g;
        if (g < 16) { int idx = n1e + g; if (idx < n1p) lst1[idx] = ZROW; }
        __syncthreads();
    }

    // finals: h_n (2,B,H) then c_n (2,B,H) after the (B,S,H) output
    if (g < HID) {
        const size_t HN = (size_t)BATCH * SEQ * HID;
        const size_t CN = HN + (size_t)2 * BATCH * HID;
        out[HN + ((size_t)0 * BATCH + b) * HID + g] = (c0s[g] > 0.f) ? 1.f : 0.f;
        out[HN + ((size_t)1 * BATCH + b) * HID + g] = (c1s[g] > 0.f) ? 1.f : 0.f;
        out[CN + ((size_t)0 * BATCH + b) * HID + g] = c0s[g];
        out[CN + ((size_t)1 * BATCH + b) * HID + g] = c1s[g];
    }
}

// ---------------------------------------------------------------
extern "C" void kernel_launch(void* const* d_in, const int* in_sizes, int n_in,
                              void* d_out, int out_size)
{
    const float* x   = (const float*)d_in[0];
    const float* Wi0 = (const float*)d_in[1];
    const float* bi0 = (const float*)d_in[2];
    const float* Wh0 = (const float*)d_in[3];
    const float* bh0 = (const float*)d_in[4];
    const float* Wi1 = (const float*)d_in[5];
    const float* bi1 = (const float*)d_in[6];
    const float* Wh1 = (const float*)d_in[7];
    const float* bh1 = (const float*)d_in[8];
    float* out = (float*)d_out;

    prep_kernel<<<1632, 256>>>(Wh0, Wi1, Wh1);

    dim3 gg(2048, 8);
    gemm_gx_kernel<<<gg, 256>>>(x, Wi0, bi0, bh0);

    recurrent_kernel<<<BATCH, 512>>>(bi1, bh1, out);
}